// round 2
// baseline (speedup 1.0000x reference)
#include <cuda_runtime.h>

// ---------------- problem constants ----------------
#define B_   2
#define L_   2048
#define D_   512
#define P_   32
#define M_   1024
#define H_   8
#define HD_  64
#define WIN_ 256
#define S_   (P_ + L_)     // 2080
#define R_   (B_ * S_)     // 4160
#define EPS_ 1e-5f

// ---------------- scratch (device globals, no allocation) ----------------
__device__ float g_combined[R_ * D_];
__device__ float g_k[R_ * D_];
__device__ float g_v[R_ * D_];
__device__ float g_q[R_ * D_];
__device__ float g_w[R_ * M_];          // reused: w_write then w_read
__device__ float g_state[B_ * M_ * D_];
__device__ float g_memout[R_ * D_];
__device__ float g_h[R_ * D_];
__device__ float g_qh[R_ * D_];
__device__ float g_kh[R_ * D_];
__device__ float g_vh[R_ * D_];
__device__ float g_aout[R_ * D_];
__device__ float g_ao2[R_ * D_];
__device__ float g_h2[R_ * D_];

// ---------------- concat: combined = [persistent ; x] ----------------
__global__ void concat_kernel(const float* __restrict__ x,
                              const float* __restrict__ pm,
                              float* __restrict__ c) {
    long i = (long)blockIdx.x * 256 + threadIdx.x;
    if (i >= (long)R_ * D_) return;
    int d = (int)(i % D_);
    long sd = i / D_;
    int s = (int)(sd % S_);
    int b = (int)(sd / S_);
    c[i] = (s < P_) ? pm[s * D_ + d]
                    : x[((long)b * L_ + (s - P_)) * D_ + d];
}

// ---------------- generic fp32 tiled GEMM ----------------
// C[M x N] = A @ B  (+ optional bias on N)
// AMODE=0: A stored row-major M x K.  AMODE=1: A stored K x M (i.e. use A^T).
// BMODE=0: B stored row-major K x N.  BMODE=1: B stored N x K (i.e. use B^T).
// Batched via blockIdx.z with element strides sA/sB/sC.
// Requirements: K % 8 == 0, N % 128 == 0 (M is guarded).
template<int AMODE, int BMODE>
__global__ void __launch_bounds__(256)
gemm_kernel(const float* __restrict__ A, const float* __restrict__ Bm,
            float* __restrict__ C, int M, int N, int K,
            long sA, long sB, long sC, const float* __restrict__ bias) {
    constexpr int BMt = 128, BNt = 128, BKt = 8;
    __shared__ float As[BKt][BMt];
    __shared__ float Bs[BKt][BNt];
    A  += (long)blockIdx.z * sA;
    Bm += (long)blockIdx.z * sB;
    C  += (long)blockIdx.z * sC;
    const int m0 = blockIdx.y * BMt, n0 = blockIdx.x * BNt;
    const int tid = threadIdx.x;
    const int tx = tid & 15, ty = tid >> 4;
    float acc[8][8];
#pragma unroll
    for (int i = 0; i < 8; i++)
#pragma unroll
        for (int j = 0; j < 8; j++) acc[i][j] = 0.f;

    for (int k0 = 0; k0 < K; k0 += BKt) {
        if (AMODE == 0) {
            int row = tid >> 1;
            int kq  = (tid & 1) << 2;
            float4 a = make_float4(0.f, 0.f, 0.f, 0.f);
            if (m0 + row < M)
                a = *(const float4*)(A + (long)(m0 + row) * K + (k0 + kq));
            As[kq + 0][row] = a.x; As[kq + 1][row] = a.y;
            As[kq + 2][row] = a.z; As[kq + 3][row] = a.w;
        } else {
            int k  = tid >> 5;
            int mq = (tid & 31) << 2;
            float4 a = make_float4(0.f, 0.f, 0.f, 0.f);
            if (m0 + mq < M)
                a = *(const float4*)(A + (long)(k0 + k) * M + (m0 + mq));
            *(float4*)&As[k][mq] = a;
        }
        if (BMODE == 0) {
            int k  = tid >> 5;
            int nq = (tid & 31) << 2;
            float4 b = *(const float4*)(Bm + (long)(k0 + k) * N + (n0 + nq));
            *(float4*)&Bs[k][nq] = b;
        } else {
            int col = tid >> 1;
            int kq  = (tid & 1) << 2;
            float4 b = make_float4(0.f, 0.f, 0.f, 0.f);
            if (n0 + col < N)
                b = *(const float4*)(Bm + (long)(n0 + col) * K + (k0 + kq));
            Bs[kq + 0][col] = b.x; Bs[kq + 1][col] = b.y;
            Bs[kq + 2][col] = b.z; Bs[kq + 3][col] = b.w;
        }
        __syncthreads();
#pragma unroll
        for (int k = 0; k < BKt; k++) {
            float a[8], b[8];
#pragma unroll
            for (int i = 0; i < 8; i++) a[i] = As[k][ty * 8 + i];
#pragma unroll
            for (int j = 0; j < 8; j++) b[j] = Bs[k][tx * 8 + j];
#pragma unroll
            for (int i = 0; i < 8; i++)
#pragma unroll
                for (int j = 0; j < 8; j++) acc[i][j] += a[i] * b[j];
        }
        __syncthreads();
    }
#pragma unroll
    for (int i = 0; i < 8; i++) {
        int m = m0 + ty * 8 + i;
        if (m < M) {
            float* crow = C + (long)m * N + n0 + tx * 8;
#pragma unroll
            for (int j = 0; j < 8; j += 4) {
                float4 o = make_float4(acc[i][j], acc[i][j + 1],
                                       acc[i][j + 2], acc[i][j + 3]);
                if (bias) {
                    const float* bp = bias + n0 + tx * 8 + j;
                    o.x += bp[0]; o.y += bp[1]; o.z += bp[2]; o.w += bp[3];
                }
                *(float4*)(crow + j) = o;
            }
        }
    }
}

// ---------------- row softmax over 1024 cols ----------------
__global__ void __launch_bounds__(256) softmax1024(float* __restrict__ w) {
    __shared__ float sh[8];
    float* row = w + (long)blockIdx.x * M_;
    const int tid = threadIdx.x;
    float4 v = *(float4*)(row + tid * 4);
    float mx = fmaxf(fmaxf(v.x, v.y), fmaxf(v.z, v.w));
#pragma unroll
    for (int o = 16; o; o >>= 1) mx = fmaxf(mx, __shfl_xor_sync(~0u, mx, o));
    if ((tid & 31) == 0) sh[tid >> 5] = mx;
    __syncthreads();
    mx = sh[0];
#pragma unroll
    for (int i = 1; i < 8; i++) mx = fmaxf(mx, sh[i]);
    v.x = __expf(v.x - mx); v.y = __expf(v.y - mx);
    v.z = __expf(v.z - mx); v.w = __expf(v.w - mx);
    float s = v.x + v.y + v.z + v.w;
#pragma unroll
    for (int o = 16; o; o >>= 1) s += __shfl_xor_sync(~0u, s, o);
    __syncthreads();
    if ((tid & 31) == 0) sh[tid >> 5] = s;
    __syncthreads();
    s = sh[0] + sh[1] + sh[2] + sh[3] + sh[4] + sh[5] + sh[6] + sh[7];
    float inv = 1.f / s;
    v.x *= inv; v.y *= inv; v.z *= inv; v.w *= inv;
    *(float4*)(row + tid * 4) = v;
}

// ---------------- layernorm, row width 512, 128 threads ----------------
__global__ void __launch_bounds__(128)
layernorm512(const float* __restrict__ in, float* __restrict__ out,
             const float* __restrict__ gw, const float* __restrict__ bw) {
    __shared__ float sh[4];
    const int tid = threadIdx.x;
    const float* row = in + (long)blockIdx.x * D_;
    float4 v = *(const float4*)(row + tid * 4);
    float s = v.x + v.y + v.z + v.w;
#pragma unroll
    for (int o = 16; o; o >>= 1) s += __shfl_xor_sync(~0u, s, o);
    if ((tid & 31) == 0) sh[tid >> 5] = s;
    __syncthreads();
    float mu = (sh[0] + sh[1] + sh[2] + sh[3]) * (1.f / 512.f);
    float dx = v.x - mu, dy = v.y - mu, dz = v.z - mu, dw = v.w - mu;
    float sq = dx * dx + dy * dy + dz * dz + dw * dw;
#pragma unroll
    for (int o = 16; o; o >>= 1) sq += __shfl_xor_sync(~0u, sq, o);
    __syncthreads();
    if ((tid & 31) == 0) sh[tid >> 5] = sq;
    __syncthreads();
    float var = (sh[0] + sh[1] + sh[2] + sh[3]) * (1.f / 512.f);
    float inv = rsqrtf(var + EPS_);
    float4 g4 = *(const float4*)(gw + tid * 4);
    float4 b4 = *(const float4*)(bw + tid * 4);
    float4 o;
    o.x = dx * inv * g4.x + b4.x;
    o.y = dy * inv * g4.y + b4.y;
    o.z = dz * inv * g4.z + b4.z;
    o.w = dw * inv * g4.w + b4.w;
    *(float4*)(out + (long)blockIdx.x * D_ + tid * 4) = o;
}

// ---------------- banded flash attention ----------------
// grid: (ceil(S/64), H, B), 256 threads. thread = (row r in 0..63, colgroup cg in 0..3)
// Online softmax over key tiles inside |i-j| < WIN.
#define ATTN_SMEM_FLOATS (64 * 65 * 2 + 64 * 64 * 2)
__global__ void __launch_bounds__(256)
attn_kernel(const float* __restrict__ qh, const float* __restrict__ kh,
            const float* __restrict__ vh, float* __restrict__ out) {
    extern __shared__ float smem[];
    float (*Qs)[65] = (float (*)[65])smem;                 // 64x65
    float (*Ps)[65] = (float (*)[65])(smem + 64 * 65);     // 64x65
    float (*Ks)[64] = (float (*)[64])(smem + 64 * 65 * 2); // 64x64
    float (*Vs)[64] = (float (*)[64])(smem + 64 * 65 * 2 + 64 * 64);

    const int qt = blockIdx.x, h = blockIdx.y, b = blockIdx.z;
    const int q0 = qt * 64;
    const int tid = threadIdx.x;
    const int r = tid >> 2, cg = tid & 3;
    const long base = (long)b * S_ * D_ + h * HD_;

    for (int i = tid; i < 64 * 64; i += 256) {
        int rr = i >> 6, dd = i & 63;
        Qs[rr][dd] = (q0 + rr < S_) ? qh[base + (long)(q0 + rr) * D_ + dd] : 0.f;
    }

    float m = -1e30f, l = 0.f;
    float o[16];
#pragma unroll
    for (int i = 0; i < 16; i++) o[i] = 0.f;

    int klo = q0 - (WIN_ - 1); if (klo < 0) klo = 0;
    int khi = q0 + 63 + WIN_ - 1; if (khi > S_ - 1) khi = S_ - 1;

    for (int kt = klo >> 6; kt <= khi >> 6; ++kt) {
        const int k0 = kt << 6;
        __syncthreads();   // protect Ks/Vs/Ps from previous iteration
        for (int i = tid; i < 64 * 64; i += 256) {
            int rr = i >> 6, dd = i & 63;
            bool ok = (k0 + rr < S_);
            long g = base + (long)(k0 + rr) * D_ + dd;
            Ks[rr][dd] = ok ? kh[g] : 0.f;
            Vs[rr][dd] = ok ? vh[g] : 0.f;
        }
        __syncthreads();

        float sreg[16];
#pragma unroll
        for (int j = 0; j < 16; j++) sreg[j] = 0.f;
#pragma unroll 8
        for (int d = 0; d < 64; d++) {
            float qd = Qs[r][d];
#pragma unroll
            for (int j = 0; j < 16; j++) sreg[j] += qd * Ks[cg * 16 + j][d];
        }

        const int qi = q0 + r;
        float tmax = -1e30f;
#pragma unroll
        for (int j = 0; j < 16; j++) {
            int kj = k0 + cg * 16 + j;
            int diff = qi - kj; if (diff < 0) diff = -diff;
            bool valid = (kj < S_) && (diff < WIN_);
            sreg[j] = valid ? sreg[j] * 0.125f : -1e30f;
            tmax = fmaxf(tmax, sreg[j]);
        }
        tmax = fmaxf(tmax, __shfl_xor_sync(0xffffffffu, tmax, 1));
        tmax = fmaxf(tmax, __shfl_xor_sync(0xffffffffu, tmax, 2));
        float mnew = fmaxf(m, tmax);
        float alpha = __expf(m - mnew);
        float lsum = 0.f;
#pragma unroll
        for (int j = 0; j < 16; j++) {
            // masked entries (sentinel -1e30) MUST contribute exactly 0, even
            // when mnew is itself the sentinel (fully-masked tile for this row):
            // exp(-1e30 - (-1e30)) = exp(0) = 1 would corrupt l and o.
            float p = (sreg[j] > -0.9e30f) ? __expf(sreg[j] - mnew) : 0.f;
            Ps[r][cg * 16 + j] = p;
            lsum += p;
        }
        lsum += __shfl_xor_sync(0xffffffffu, lsum, 1);
        lsum += __shfl_xor_sync(0xffffffffu, lsum, 2);
        l = l * alpha + lsum;
        m = mnew;
#pragma unroll
        for (int i = 0; i < 16; i++) o[i] *= alpha;
        __syncthreads();   // Ps visible to all 4 lanes of each row
#pragma unroll 4
        for (int j = 0; j < 64; j++) {
            float p = Ps[r][j];
#pragma unroll
            for (int i = 0; i < 16; i++) o[i] += p * Vs[j][cg * 16 + i];
        }
    }

    const int qi = q0 + r;
    if (qi < S_) {
        float inv = 1.f / l;
        float* orow = out + base + (long)qi * D_ + cg * 16;
#pragma unroll
        for (int i = 0; i < 16; i++) orow[i] = o[i] * inv;
    }
}

// ---------------- launch ----------------
extern "C" void kernel_launch(void* const* d_in, const int* in_sizes, int n_in,
                              void* d_out, int out_size) {
    const float* x        = (const float*)d_in[0];
    const float* pm       = (const float*)d_in[1];
    const float* mem_keys = (const float*)d_in[2];
    const float* mem_Wk   = (const float*)d_in[3];
    const float* mem_Wv   = (const float*)d_in[4];
    const float* mem_Wq   = (const float*)d_in[5];
    const float* attn_Wq  = (const float*)d_in[6];
    const float* attn_Wk  = (const float*)d_in[7];
    const float* attn_Wv  = (const float*)d_in[8];
    const float* attn_Wo  = (const float*)d_in[9];
    const float* ln1_g    = (const float*)d_in[10];
    const float* ln1_b    = (const float*)d_in[11];
    const float* ln2_g    = (const float*)d_in[12];
    const float* ln2_b    = (const float*)d_in[13];
    const float* out_W    = (const float*)d_in[14];
    const float* out_b    = (const float*)d_in[15];
    float* out = (float*)d_out;

    float *combined, *k, *v, *q, *w, *state, *memout, *h;
    float *qh, *kh, *vh, *aout, *ao2, *h2;
    cudaGetSymbolAddress((void**)&combined, g_combined);
    cudaGetSymbolAddress((void**)&k, g_k);
    cudaGetSymbolAddress((void**)&v, g_v);
    cudaGetSymbolAddress((void**)&q, g_q);
    cudaGetSymbolAddress((void**)&w, g_w);
    cudaGetSymbolAddress((void**)&state, g_state);
    cudaGetSymbolAddress((void**)&memout, g_memout);
    cudaGetSymbolAddress((void**)&h, g_h);
    cudaGetSymbolAddress((void**)&qh, g_qh);
    cudaGetSymbolAddress((void**)&kh, g_kh);
    cudaGetSymbolAddress((void**)&vh, g_vh);
    cudaGetSymbolAddress((void**)&aout, g_aout);
    cudaGetSymbolAddress((void**)&ao2, g_ao2);
    cudaGetSymbolAddress((void**)&h2, g_h2);

    // Unconditional (no static guard — every call must do identical work).
    // cudaFuncSetAttribute is idempotent and capture-safe.
    cudaFuncSetAttribute(attn_kernel,
                         cudaFuncAttributeMaxDynamicSharedMemorySize,
                         ATTN_SMEM_FLOATS * (int)sizeof(float));

    // 1. combined = [pm ; x]
    concat_kernel<<<(int)(((long)R_ * D_ + 255) / 256), 256>>>(x, pm, combined);

    const dim3 g512(512 / 128, (R_ + 127) / 128, 1);   // N=512, M=4160
    const dim3 g1024(1024 / 128, (R_ + 127) / 128, 1); // N=1024, M=4160

    // 2. memory k/v/q projections
    gemm_kernel<0, 0><<<g512, 256>>>(combined, mem_Wk, k, R_, D_, D_, 0, 0, 0, nullptr);
    gemm_kernel<0, 0><<<g512, 256>>>(combined, mem_Wv, v, R_, D_, D_, 0, 0, 0, nullptr);
    gemm_kernel<0, 0><<<g512, 256>>>(combined, mem_Wq, q, R_, D_, D_, 0, 0, 0, nullptr);

    // 3. write weights: softmax(k @ mem_keys^T)
    gemm_kernel<0, 1><<<g1024, 256>>>(k, mem_keys, w, R_, M_, D_, 0, 0, 0, nullptr);
    softmax1024<<<R_, 256>>>(w);

    // 4. state[b] = w_write[b]^T @ v[b]   (M=1024, N=512, K=S)
    {
        dim3 gs(512 / 128, 1024 / 128, B_);
        gemm_kernel<1, 0><<<gs, 256>>>(w, v, state, M_, D_, S_,
                                       (long)S_ * M_, (long)S_ * D_, (long)M_ * D_, nullptr);
    }

    // 5. read weights: softmax(q @ mem_keys^T)   (overwrites w)
    gemm_kernel<0, 1><<<g1024, 256>>>(q, mem_keys, w, R_, M_, D_, 0, 0, 0, nullptr);
    softmax1024<<<R_, 256>>>(w);

    // 6. mem_out[b] = w_read[b] @ state[b]   (M=S, N=512, K=1024)
    {
        dim3 gm(512 / 128, (S_ + 127) / 128, B_);
        gemm_kernel<0, 0><<<gm, 256>>>(w, state, memout, S_, D_, M_,
                                       (long)S_ * M_, (long)M_ * D_, (long)S_ * D_, nullptr);
    }

    // 7. LN1
    layernorm512<<<R_, 128>>>(memout, h, ln1_g, ln1_b);

    // 8. attention projections
    gemm_kernel<0, 0><<<g512, 256>>>(h, attn_Wq, qh, R_, D_, D_, 0, 0, 0, nullptr);
    gemm_kernel<0, 0><<<g512, 256>>>(h, attn_Wk, kh, R_, D_, D_, 0, 0, 0, nullptr);
    gemm_kernel<0, 0><<<g512, 256>>>(h, attn_Wv, vh, R_, D_, D_, 0, 0, 0, nullptr);

    // 9. banded flash attention
    {
        dim3 ga((S_ + 63) / 64, H_, B_);
        attn_kernel<<<ga, 256, ATTN_SMEM_FLOATS * (int)sizeof(float)>>>(qh, kh, vh, aout);
    }

    // 10. output projection + LN2 + final linear (+bias)
    gemm_kernel<0, 0><<<g512, 256>>>(aout, attn_Wo, ao2, R_, D_, D_, 0, 0, 0, nullptr);
    layernorm512<<<R_, 128>>>(ao2, h2, ln2_g, ln2_b);
    gemm_kernel<0, 0><<<g512, 256>>>(h2, out_W, out, R_, D_, D_, 0, 0, 0, out_b);
}

// round 3
// speedup vs baseline: 1.2817x; 1.2817x over previous
#include <cuda_runtime.h>

// ---------------- problem constants ----------------
#define B_   2
#define L_   2048
#define D_   512
#define P_   32
#define M_   1024
#define H_   8
#define HD_  64
#define WIN_ 256
#define S_   (P_ + L_)     // 2080
#define R_   (B_ * S_)     // 4160
#define EPS_ 1e-5f

// ---------------- scratch (device globals, no allocation) ----------------
__device__ float g_combined[R_ * D_];
__device__ float g_k[R_ * D_];
__device__ float g_v[R_ * D_];
__device__ float g_q[R_ * D_];
__device__ float g_w[R_ * M_];          // reused: w_write then w_read
__device__ float g_state[B_ * M_ * D_];
__device__ float g_memout[R_ * D_];
__device__ float g_h[R_ * D_];
__device__ float g_qh[R_ * D_];
__device__ float g_kh[R_ * D_];
__device__ float g_vh[R_ * D_];
__device__ float g_aout[R_ * D_];
__device__ float g_ao2[R_ * D_];
__device__ float g_h2[R_ * D_];

// ---------------- concat: combined = [persistent ; x] ----------------
__global__ void concat_kernel(const float* __restrict__ x,
                              const float* __restrict__ pm,
                              float* __restrict__ c) {
    long i = (long)blockIdx.x * 256 + threadIdx.x;
    if (i >= (long)R_ * D_) return;
    int d = (int)(i % D_);
    long sd = i / D_;
    int s = (int)(sd % S_);
    int b = (int)(sd / S_);
    c[i] = (s < P_) ? pm[s * D_ + d]
                    : x[((long)b * L_ + (s - P_)) * D_ + d];
}

// ---------------- fp32 GEMM core: 64x128x16 tile, 256 threads ----------------
// C[M x N] = A @ B (+ optional bias over N).
// AMODE=0: A row-major M x K.  AMODE=1: A stored K x M (use A^T, leading dim M).
// BMODE=0: B row-major K x N.  BMODE=1: B stored N x K (use B^T, leading dim K).
// Requirements: K % 16 == 0, N % 128 == 0; M guarded.
// Each thread computes 4 rows x 8 cols (cols tx*4 and 64+tx*4: conflict-free LDS.128).
template<int AMODE, int BMODE>
__device__ __forceinline__ void gemm_core(
    const float* __restrict__ A, const float* __restrict__ Bm,
    float* __restrict__ C, int M, int N, int K, const float* __restrict__ bias) {
    __shared__ float As[16][64];
    __shared__ float Bs[16][128];
    const int tid = threadIdx.x;
    const int tx = tid & 15, ty = tid >> 4;
    const int m0 = blockIdx.y * 64, n0 = blockIdx.x * 128;

    float acc[4][8];
#pragma unroll
    for (int i = 0; i < 4; i++)
#pragma unroll
        for (int j = 0; j < 8; j++) acc[i][j] = 0.f;

    float4 ra, rb0, rb1;

    // --- staging loads (global -> regs) ---
    auto loadA = [&](int k0) {
        if (AMODE == 0) {
            int row = tid >> 2, kq = (tid & 3) << 2;
            ra = (m0 + row < M)
               ? *(const float4*)(A + (long)(m0 + row) * K + (k0 + kq))
               : make_float4(0.f, 0.f, 0.f, 0.f);
        } else {
            int k = tid >> 4, mq = (tid & 15) << 2;
            ra = (m0 + mq < M)
               ? *(const float4*)(A + (long)(k0 + k) * M + (m0 + mq))
               : make_float4(0.f, 0.f, 0.f, 0.f);
        }
    };
    auto loadB = [&](int k0) {
        if (BMODE == 0) {
            int k = tid >> 5, nq = (tid & 31) << 2;
            rb0 = *(const float4*)(Bm + (long)(k0 + k) * N + (n0 + nq));
            rb1 = *(const float4*)(Bm + (long)(k0 + k + 8) * N + (n0 + nq));
        } else {
            int col = tid >> 1, kq = (tid & 1) << 3;
            rb0 = *(const float4*)(Bm + (long)(n0 + col) * K + (k0 + kq));
            rb1 = *(const float4*)(Bm + (long)(n0 + col) * K + (k0 + kq + 4));
        }
    };
    // --- staging stores (regs -> smem) ---
    auto storeA = [&]() {
        if (AMODE == 0) {
            int row = tid >> 2, kq = (tid & 3) << 2;
            As[kq + 0][row] = ra.x; As[kq + 1][row] = ra.y;
            As[kq + 2][row] = ra.z; As[kq + 3][row] = ra.w;
        } else {
            int k = tid >> 4, mq = (tid & 15) << 2;
            *(float4*)&As[k][mq] = ra;
        }
    };
    auto storeB = [&]() {
        if (BMODE == 0) {
            int k = tid >> 5, nq = (tid & 31) << 2;
            *(float4*)&Bs[k][nq]     = rb0;
            *(float4*)&Bs[k + 8][nq] = rb1;
        } else {
            int col = tid >> 1, kq = (tid & 1) << 3;
            Bs[kq + 0][col] = rb0.x; Bs[kq + 1][col] = rb0.y;
            Bs[kq + 2][col] = rb0.z; Bs[kq + 3][col] = rb0.w;
            Bs[kq + 4][col] = rb1.x; Bs[kq + 5][col] = rb1.y;
            Bs[kq + 6][col] = rb1.z; Bs[kq + 7][col] = rb1.w;
        }
    };

    loadA(0); loadB(0);
    storeA(); storeB();
    __syncthreads();

    for (int k0 = 16; k0 <= K; k0 += 16) {
        const bool last = (k0 == K);
        if (!last) { loadA(k0); loadB(k0); }   // prefetch next slab into regs
#pragma unroll
        for (int k = 0; k < 16; k++) {
            float a[4], b[8];
            *(float4*)a       = *(const float4*)&As[k][ty * 4];
            *(float4*)b       = *(const float4*)&Bs[k][tx * 4];
            *(float4*)(b + 4) = *(const float4*)&Bs[k][64 + tx * 4];
#pragma unroll
            for (int i = 0; i < 4; i++)
#pragma unroll
                for (int j = 0; j < 8; j++) acc[i][j] += a[i] * b[j];
        }
        __syncthreads();
        if (!last) { storeA(); storeB(); __syncthreads(); }
    }

    // --- epilogue ---
    float4 bia0 = make_float4(0.f, 0.f, 0.f, 0.f), bia1 = bia0;
    if (bias) {
        bia0 = *(const float4*)(bias + n0 + tx * 4);
        bia1 = *(const float4*)(bias + n0 + 64 + tx * 4);
    }
#pragma unroll
    for (int i = 0; i < 4; i++) {
        int m = m0 + ty * 4 + i;
        if (m < M) {
            float* crow = C + (long)m * N + n0;
            float4 o0 = make_float4(acc[i][0] + bia0.x, acc[i][1] + bia0.y,
                                    acc[i][2] + bia0.z, acc[i][3] + bia0.w);
            float4 o1 = make_float4(acc[i][4] + bia1.x, acc[i][5] + bia1.y,
                                    acc[i][6] + bia1.z, acc[i][7] + bia1.w);
            *(float4*)(crow + tx * 4)      = o0;
            *(float4*)(crow + 64 + tx * 4) = o1;
        }
    }
}

template<int AMODE, int BMODE>
__global__ void __launch_bounds__(256, 3)
gemm_kernel(const float* __restrict__ A, const float* __restrict__ Bm,
            float* __restrict__ C, int M, int N, int K,
            long sA, long sB, long sC, const float* __restrict__ bias) {
    A  += (long)blockIdx.z * sA;
    Bm += (long)blockIdx.z * sB;
    C  += (long)blockIdx.z * sC;
    gemm_core<AMODE, BMODE>(A, Bm, C, M, N, K, bias);
}

// 3 GEMMs sharing the same A, distinct B/C, selected by blockIdx.z.
struct Ptr3 { const float* b0; const float* b1; const float* b2;
              float* c0; float* c1; float* c2; };
__global__ void __launch_bounds__(256, 3)
gemm3_kernel(const float* __restrict__ A, Ptr3 p, int M, int N, int K) {
    const float* Bm = (blockIdx.z == 0) ? p.b0 : (blockIdx.z == 1) ? p.b1 : p.b2;
    float*       C  = (blockIdx.z == 0) ? p.c0 : (blockIdx.z == 1) ? p.c1 : p.c2;
    gemm_core<0, 0>(A, Bm, C, M, N, K, nullptr);
}

// ---------------- row softmax over 1024 cols ----------------
__global__ void __launch_bounds__(256) softmax1024(float* __restrict__ w) {
    __shared__ float sh[8];
    float* row = w + (long)blockIdx.x * M_;
    const int tid = threadIdx.x;
    float4 v = *(float4*)(row + tid * 4);
    float mx = fmaxf(fmaxf(v.x, v.y), fmaxf(v.z, v.w));
#pragma unroll
    for (int o = 16; o; o >>= 1) mx = fmaxf(mx, __shfl_xor_sync(~0u, mx, o));
    if ((tid & 31) == 0) sh[tid >> 5] = mx;
    __syncthreads();
    mx = sh[0];
#pragma unroll
    for (int i = 1; i < 8; i++) mx = fmaxf(mx, sh[i]);
    v.x = __expf(v.x - mx); v.y = __expf(v.y - mx);
    v.z = __expf(v.z - mx); v.w = __expf(v.w - mx);
    float s = v.x + v.y + v.z + v.w;
#pragma unroll
    for (int o = 16; o; o >>= 1) s += __shfl_xor_sync(~0u, s, o);
    __syncthreads();
    if ((tid & 31) == 0) sh[tid >> 5] = s;
    __syncthreads();
    s = sh[0] + sh[1] + sh[2] + sh[3] + sh[4] + sh[5] + sh[6] + sh[7];
    float inv = 1.f / s;
    v.x *= inv; v.y *= inv; v.z *= inv; v.w *= inv;
    *(float4*)(row + tid * 4) = v;
}

// ---------------- layernorm, row width 512, 128 threads ----------------
__global__ void __launch_bounds__(128)
layernorm512(const float* __restrict__ in, float* __restrict__ out,
             const float* __restrict__ gw, const float* __restrict__ bw) {
    __shared__ float sh[4];
    const int tid = threadIdx.x;
    const float* row = in + (long)blockIdx.x * D_;
    float4 v = *(const float4*)(row + tid * 4);
    float s = v.x + v.y + v.z + v.w;
#pragma unroll
    for (int o = 16; o; o >>= 1) s += __shfl_xor_sync(~0u, s, o);
    if ((tid & 31) == 0) sh[tid >> 5] = s;
    __syncthreads();
    float mu = (sh[0] + sh[1] + sh[2] + sh[3]) * (1.f / 512.f);
    float dx = v.x - mu, dy = v.y - mu, dz = v.z - mu, dw = v.w - mu;
    float sq = dx * dx + dy * dy + dz * dz + dw * dw;
#pragma unroll
    for (int o = 16; o; o >>= 1) sq += __shfl_xor_sync(~0u, sq, o);
    __syncthreads();
    if ((tid & 31) == 0) sh[tid >> 5] = sq;
    __syncthreads();
    float var = (sh[0] + sh[1] + sh[2] + sh[3]) * (1.f / 512.f);
    float inv = rsqrtf(var + EPS_);
    float4 g4 = *(const float4*)(gw + tid * 4);
    float4 b4 = *(const float4*)(bw + tid * 4);
    float4 o;
    o.x = dx * inv * g4.x + b4.x;
    o.y = dy * inv * g4.y + b4.y;
    o.z = dz * inv * g4.z + b4.z;
    o.w = dw * inv * g4.w + b4.w;
    *(float4*)(out + (long)blockIdx.x * D_ + tid * 4) = o;
}

// ---------------- banded flash attention ----------------
// grid: (ceil(S/64), H, B), 256 threads. thread = (row r in 0..63, colgroup cg in 0..3)
// Online softmax over key tiles inside |i-j| < WIN.
#define ATTN_SMEM_FLOATS (64 * 65 * 2 + 64 * 64 * 2)
__global__ void __launch_bounds__(256)
attn_kernel(const float* __restrict__ qh, const float* __restrict__ kh,
            const float* __restrict__ vh, float* __restrict__ out) {
    extern __shared__ float smem[];
    float (*Qs)[65] = (float (*)[65])smem;                 // 64x65
    float (*Ps)[65] = (float (*)[65])(smem + 64 * 65);     // 64x65
    float (*Ks)[64] = (float (*)[64])(smem + 64 * 65 * 2); // 64x64
    float (*Vs)[64] = (float (*)[64])(smem + 64 * 65 * 2 + 64 * 64);

    const int qt = blockIdx.x, h = blockIdx.y, b = blockIdx.z;
    const int q0 = qt * 64;
    const int tid = threadIdx.x;
    const int r = tid >> 2, cg = tid & 3;
    const long base = (long)b * S_ * D_ + h * HD_;

    for (int i = tid; i < 64 * 64; i += 256) {
        int rr = i >> 6, dd = i & 63;
        Qs[rr][dd] = (q0 + rr < S_) ? qh[base + (long)(q0 + rr) * D_ + dd] : 0.f;
    }

    float m = -1e30f, l = 0.f;
    float o[16];
#pragma unroll
    for (int i = 0; i < 16; i++) o[i] = 0.f;

    int klo = q0 - (WIN_ - 1); if (klo < 0) klo = 0;
    int khi = q0 + 63 + WIN_ - 1; if (khi > S_ - 1) khi = S_ - 1;

    for (int kt = klo >> 6; kt <= khi >> 6; ++kt) {
        const int k0 = kt << 6;
        __syncthreads();   // protect Ks/Vs/Ps from previous iteration
        for (int i = tid; i < 64 * 64; i += 256) {
            int rr = i >> 6, dd = i & 63;
            bool ok = (k0 + rr < S_);
            long g = base + (long)(k0 + rr) * D_ + dd;
            Ks[rr][dd] = ok ? kh[g] : 0.f;
            Vs[rr][dd] = ok ? vh[g] : 0.f;
        }
        __syncthreads();

        float sreg[16];
#pragma unroll
        for (int j = 0; j < 16; j++) sreg[j] = 0.f;
#pragma unroll 8
        for (int d = 0; d < 64; d++) {
            float qd = Qs[r][d];
#pragma unroll
            for (int j = 0; j < 16; j++) sreg[j] += qd * Ks[cg * 16 + j][d];
        }

        const int qi = q0 + r;
        float tmax = -1e30f;
#pragma unroll
        for (int j = 0; j < 16; j++) {
            int kj = k0 + cg * 16 + j;
            int diff = qi - kj; if (diff < 0) diff = -diff;
            bool valid = (kj < S_) && (diff < WIN_);
            sreg[j] = valid ? sreg[j] * 0.125f : -1e30f;
            tmax = fmaxf(tmax, sreg[j]);
        }
        tmax = fmaxf(tmax, __shfl_xor_sync(0xffffffffu, tmax, 1));
        tmax = fmaxf(tmax, __shfl_xor_sync(0xffffffffu, tmax, 2));
        float mnew = fmaxf(m, tmax);
        float alpha = __expf(m - mnew);
        float lsum = 0.f;
#pragma unroll
        for (int j = 0; j < 16; j++) {
            // masked entries (sentinel -1e30) MUST contribute exactly 0, even
            // when mnew is itself the sentinel (fully-masked tile for this row).
            float p = (sreg[j] > -0.9e30f) ? __expf(sreg[j] - mnew) : 0.f;
            Ps[r][cg * 16 + j] = p;
            lsum += p;
        }
        lsum += __shfl_xor_sync(0xffffffffu, lsum, 1);
        lsum += __shfl_xor_sync(0xffffffffu, lsum, 2);
        l = l * alpha + lsum;
        m = mnew;
#pragma unroll
        for (int i = 0; i < 16; i++) o[i] *= alpha;
        __syncthreads();   // Ps visible to all 4 lanes of each row
#pragma unroll 4
        for (int j = 0; j < 64; j++) {
            float p = Ps[r][j];
#pragma unroll
            for (int i = 0; i < 16; i++) o[i] += p * Vs[j][cg * 16 + i];
        }
    }

    const int qi = q0 + r;
    if (qi < S_) {
        float inv = 1.f / l;
        float* orow = out + base + (long)qi * D_ + cg * 16;
#pragma unroll
        for (int i = 0; i < 16; i++) orow[i] = o[i] * inv;
    }
}

// ---------------- launch ----------------
extern "C" void kernel_launch(void* const* d_in, const int* in_sizes, int n_in,
                              void* d_out, int out_size) {
    const float* x        = (const float*)d_in[0];
    const float* pm       = (const float*)d_in[1];
    const float* mem_keys = (const float*)d_in[2];
    const float* mem_Wk   = (const float*)d_in[3];
    const float* mem_Wv   = (const float*)d_in[4];
    const float* mem_Wq   = (const float*)d_in[5];
    const float* attn_Wq  = (const float*)d_in[6];
    const float* attn_Wk  = (const float*)d_in[7];
    const float* attn_Wv  = (const float*)d_in[8];
    const float* attn_Wo  = (const float*)d_in[9];
    const float* ln1_g    = (const float*)d_in[10];
    const float* ln1_b    = (const float*)d_in[11];
    const float* ln2_g    = (const float*)d_in[12];
    const float* ln2_b    = (const float*)d_in[13];
    const float* out_W    = (const float*)d_in[14];
    const float* out_b    = (const float*)d_in[15];
    float* out = (float*)d_out;

    float *combined, *k, *v, *q, *w, *state, *memout, *h;
    float *qh, *kh, *vh, *aout, *ao2, *h2;
    cudaGetSymbolAddress((void**)&combined, g_combined);
    cudaGetSymbolAddress((void**)&k, g_k);
    cudaGetSymbolAddress((void**)&v, g_v);
    cudaGetSymbolAddress((void**)&q, g_q);
    cudaGetSymbolAddress((void**)&w, g_w);
    cudaGetSymbolAddress((void**)&state, g_state);
    cudaGetSymbolAddress((void**)&memout, g_memout);
    cudaGetSymbolAddress((void**)&h, g_h);
    cudaGetSymbolAddress((void**)&qh, g_qh);
    cudaGetSymbolAddress((void**)&kh, g_kh);
    cudaGetSymbolAddress((void**)&vh, g_vh);
    cudaGetSymbolAddress((void**)&aout, g_aout);
    cudaGetSymbolAddress((void**)&ao2, g_ao2);
    cudaGetSymbolAddress((void**)&h2, g_h2);

    // Unconditional (no static guard). Idempotent and capture-safe.
    cudaFuncSetAttribute(attn_kernel,
                         cudaFuncAttributeMaxDynamicSharedMemorySize,
                         ATTN_SMEM_FLOATS * (int)sizeof(float));

    // 1. combined = [pm ; x]
    concat_kernel<<<(int)(((long)R_ * D_ + 255) / 256), 256>>>(x, pm, combined);

    const int MT = (R_ + 63) / 64;                 // 65 row tiles for 4160 rows
    const dim3 g512(512 / 128, MT, 1);             // 260 CTAs
    const dim3 g1024(1024 / 128, MT, 1);           // 520 CTAs

    // 2. memory k/v/q projections (one batched launch, 780 CTAs)
    {
        Ptr3 p{mem_Wk, mem_Wv, mem_Wq, k, v, q};
        dim3 g(512 / 128, MT, 3);
        gemm3_kernel<<<g, 256>>>(combined, p, R_, D_, D_);
    }

    // 3. write weights: softmax(k @ mem_keys^T)
    gemm_kernel<0, 1><<<g1024, 256>>>(k, mem_keys, w, R_, M_, D_, 0, 0, 0, nullptr);
    softmax1024<<<R_, 256>>>(w);

    // 4. state[b] = w_write[b]^T @ v[b]   (M=1024, N=512, K=S)
    {
        dim3 gs(512 / 128, 1024 / 64, B_);
        gemm_kernel<1, 0><<<gs, 256>>>(w, v, state, M_, D_, S_,
                                       (long)S_ * M_, (long)S_ * D_, (long)M_ * D_, nullptr);
    }

    // 5. read weights: softmax(q @ mem_keys^T)   (overwrites w)
    gemm_kernel<0, 1><<<g1024, 256>>>(q, mem_keys, w, R_, M_, D_, 0, 0, 0, nullptr);
    softmax1024<<<R_, 256>>>(w);

    // 6. mem_out[b] = w_read[b] @ state[b]   (M=S, N=512, K=1024)
    {
        dim3 gm(512 / 128, (S_ + 63) / 64, B_);
        gemm_kernel<0, 0><<<gm, 256>>>(w, state, memout, S_, D_, M_,
                                       (long)S_ * M_, (long)M_ * D_, (long)S_ * D_, nullptr);
    }

    // 7. LN1
    layernorm512<<<R_, 128>>>(memout, h, ln1_g, ln1_b);

    // 8. attention projections (one batched launch)
    {
        Ptr3 p{attn_Wq, attn_Wk, attn_Wv, qh, kh, vh};
        dim3 g(512 / 128, MT, 3);
        gemm3_kernel<<<g, 256>>>(h, p, R_, D_, D_);
    }

    // 9. banded flash attention
    {
        dim3 ga((S_ + 63) / 64, H_, B_);
        attn_kernel<<<ga, 256, ATTN_SMEM_FLOATS * (int)sizeof(float)>>>(qh, kh, vh, aout);
    }

    // 10. output projection + LN2 + final linear (+bias)
    gemm_kernel<0, 0><<<g512, 256>>>(aout, attn_Wo, ao2, R_, D_, D_, 0, 0, 0, nullptr);
    layernorm512<<<R_, 128>>>(ao2, h2, ln2_g, ln2_b);
    gemm_kernel<0, 0><<<g512, 256>>>(h2, out_W, out, R_, D_, D_, 0, 0, 0, out_b);
}